// round 1
// baseline (speedup 1.0000x reference)
#include <cuda_runtime.h>
#include <math.h>

// Problem dims (hardcoded from reference setup_inputs)
#define BD 4
#define CD 16
#define HD 384
#define WD 384
#define HWD (HD*WD)
#define NITER 20

// ---------------- scratch (device globals; no allocation APIs) ----------------
__device__ float2 g_tw[384];                 // forward twiddles e^{-2pi i t/384}
__device__ float2 g_T1[BD*CD*HWD];           // 75.5 MB k-space scratch
__device__ float2 g_S[4*BD*HWD];             // 4 coil-partials of S(y)
__device__ float2 g_c0[BD*HWD];              // constant adjoint-of-data term
__device__ float2 g_Sbar[BD*HWD];            // sum_c conj(coil)
__device__ float2 g_x[BD*HWD];               // FISTA x state
__device__ float2 g_y[BD*HWD];               // FISTA y state

// ---------------- FFT helpers ----------------
__device__ __forceinline__ int pd(int i) { return i + (i >> 4); }  // bank-conflict pad
#define PBUF 408
#define NG 4

__device__ __forceinline__ float2 cmulf(float2 a, float2 b) {
    return make_float2(a.x*b.x - a.y*b.y, a.x*b.y + a.y*b.x);
}

// one radix-4 Stockham stage butterfly for thread lt (0..95)
// reads in[lt + 96*i]; writes out[o0 + k*ostep] * W384^{tbase*k} (conj if dir<0)
__device__ __forceinline__ void r4(const float2* __restrict__ in, float2* __restrict__ out,
                                   const float2* __restrict__ tw,
                                   int lt, int tbase, int o0, int ostep, float dir)
{
    float2 z0 = in[pd(lt)], z1 = in[pd(lt+96)], z2 = in[pd(lt+192)], z3 = in[pd(lt+288)];
    float ax = z0.x+z2.x, ay = z0.y+z2.y;
    float bx = z0.x-z2.x, by = z0.y-z2.y;
    float cx = z1.x+z3.x, cy = z1.y+z3.y;
    float dx = z1.x-z3.x, dy = z1.y-z3.y;
    float ix =  dir*dy,   iy = -dir*dx;           // (-i*d) fwd, (+i*d) inv
    float2 Z0 = make_float2(ax+cx, ay+cy);
    float2 Z1 = make_float2(bx+ix, by+iy);
    float2 Z2 = make_float2(ax-cx, ay-cy);
    float2 Z3 = make_float2(bx-ix, by-iy);
    out[pd(o0)] = Z0;
    float2 w1 = tw[tbase];    w1.y *= dir;
    float2 w2 = tw[2*tbase];  w2.y *= dir;
    float2 w3 = tw[3*tbase];  w3.y *= dir;
    out[pd(o0 +   ostep)] = cmulf(Z1, w1);
    out[pd(o0 + 2*ostep)] = cmulf(Z2, w2);
    out[pd(o0 + 3*ostep)] = cmulf(Z3, w3);
}

__device__ __forceinline__ void dft3(float2 a, float2 b, float2 c, float S3,
                                     float2& Z0, float2& Z1, float2& Z2)
{
    float tx = b.x+c.x, ty = b.y+c.y;
    float ux = b.x-c.x, uy = b.y-c.y;
    Z0 = make_float2(a.x+tx, a.y+ty);
    float vx = a.x - 0.5f*tx, vy = a.y - 0.5f*ty;
    Z1 = make_float2(vx + S3*uy, vy - S3*ux);
    Z2 = make_float2(vx - S3*uy, vy + S3*ux);
}

// 384-point FFT, Stockham DIF radices [4,4,4,6], 96 threads (lt), in/out in b0.
// dir=+1 forward, -1 inverse (unnormalized). Ends with __syncthreads().
__device__ __forceinline__ void fft384(float2* b0, float2* b1,
                                       const float2* tw, int lt, float dir)
{
    r4(b0, b1, tw, lt, lt, 4*lt, 1, dir);                      // n=384 s=1
    __syncthreads();
    { int p = lt>>2, q = lt&3;  r4(b1, b0, tw, lt, 4*p,  q+16*p, 4,  dir); }  // n=96 s=4
    __syncthreads();
    { int p = lt>>4, q = lt&15; r4(b0, b1, tw, lt, 16*p, q+64*p, 16, dir); }  // n=24 s=16
    __syncthreads();
    if (lt < 64) {                                             // n=6 radix-6, s=64
        float2 z0 = b1[pd(lt)],     z1 = b1[pd(lt+64)],  z2 = b1[pd(lt+128)];
        float2 z3 = b1[pd(lt+192)], z4 = b1[pd(lt+256)], z5 = b1[pd(lt+320)];
        float S3 = 0.8660254037844386f * dir;
        float2 E0,E1,E2,O0,O1,O2;
        dft3(z0, z2, z4, S3, E0, E1, E2);
        dft3(z1, z3, z5, S3, O0, O1, O2);
        float2 w6a = make_float2( 0.5f, -S3);
        float2 w6b = make_float2(-0.5f, -S3);
        float2 P1 = cmulf(O1, w6a);
        float2 P2 = cmulf(O2, w6b);
        b0[pd(lt)]     = make_float2(E0.x+O0.x, E0.y+O0.y);
        b0[pd(lt+64)]  = make_float2(E1.x+P1.x, E1.y+P1.y);
        b0[pd(lt+128)] = make_float2(E2.x+P2.x, E2.y+P2.y);
        b0[pd(lt+192)] = make_float2(E0.x-O0.x, E0.y-O0.y);
        b0[pd(lt+256)] = make_float2(E1.x-P1.x, E1.y-P1.y);
        b0[pd(lt+320)] = make_float2(E2.x-P2.x, E2.y-P2.y);
    }
    __syncthreads();
}

#define FFT_PREAMBLE                                              \
    __shared__ float2 sb[NG*2*PBUF];                              \
    __shared__ float2 stw[384];                                   \
    for (int t = threadIdx.x; t < 384; t += 384) stw[t] = g_tw[t];\
    int g  = threadIdx.x / 96;                                    \
    int lt = threadIdx.x % 96;                                    \
    float2* b0 = sb + g*(2*PBUF);                                 \
    float2* b1 = b0 + PBUF;

// ---------------- init ----------------
__global__ void init_tw_kernel()
{
    int t = threadIdx.x;
    if (t < 384) {
        float s, c;
        sincospif(-2.0f * (float)t / 384.0f, &s, &c);
        g_tw[t] = make_float2(c, s);
    }
}

// Sbar = sum_c conj(coil)
__global__ void p1_sbar(const float* __restrict__ csm)
{
    int i = blockIdx.x*blockDim.x + threadIdx.x;
    if (i >= BD*HWD) return;
    int bb = i / HWD, r = i - bb*HWD;
    float sr = 0.f, si = 0.f;
    #pragma unroll
    for (int c = 0; c < CD; c++) {
        sr += csm[((bb*2+0)*CD + c)*HWD + r];
        si -= csm[((bb*2+1)*CD + c)*HWD + r];
    }
    g_Sbar[i] = make_float2(sr, si);
}

// rows inverse FFT of (mask * b)  -> tmp (front of g_T1)
__global__ void __launch_bounds__(384) p2_rows(const float* __restrict__ x0,
                                               const int* __restrict__ mask)
{
    FFT_PREAMBLE
    int blk = blockIdx.x;
    int hq = blk % (HD/4), bb = blk / (HD/4);
    int h = hq*4 + g;
    const float* bre = x0 + (bb*2+0)*HWD + h*WD;
    const float* bim = x0 + (bb*2+1)*HWD + h*WD;
    const int*   mr  = mask + bb*HWD + h*WD;
    #pragma unroll
    for (int j = 0; j < 4; j++) {
        int w = lt + 96*j;
        float mv = (float)mr[w];
        b0[pd(w)] = make_float2(mv*bre[w], mv*bim[w]);
    }
    __syncthreads();
    fft384(b0, b1, stw, lt, -1.0f);
    const float sc = 1.0f/384.0f;
    float2* orow = g_T1 + (bb*HD + h)*WD;
    #pragma unroll
    for (int j = 0; j < 4; j++) {
        int w = lt + 96*j;
        float2 v = b0[pd(w)];
        orow[w] = make_float2(v.x*sc, v.y*sc);
    }
}

// cols inverse FFT of tmp, * Sbar  -> c0
__global__ void __launch_bounds__(384) p3_cols()
{
    FFT_PREAMBLE
    int blk = blockIdx.x;
    int wq = blk % (WD/4), bb = blk / (WD/4);
    int w = wq*4 + g;
    const float2* base = g_T1 + bb*HWD;
    #pragma unroll
    for (int j = 0; j < 4; j++) { int h = lt + 96*j; b0[pd(h)] = base[h*WD + w]; }
    __syncthreads();
    fft384(b0, b1, stw, lt, -1.0f);
    const float sc = 1.0f/384.0f;
    #pragma unroll
    for (int j = 0; j < 4; j++) {
        int h = lt + 96*j;
        float2 v = b0[pd(h)];
        v.x *= sc; v.y *= sc;
        float2 sbv = g_Sbar[bb*HWD + h*WD + w];
        g_c0[bb*HWD + h*WD + w] = cmulf(sbv, v);
    }
}

// iteration 0 (y = 0): x = y = relu((1-lam)*c0 + lam*zc)
__global__ void k4_first(const float* __restrict__ zk, const float* __restrict__ lam)
{
    int i = blockIdx.x*blockDim.x + threadIdx.x;
    if (i >= BD*HWD) return;
    int bb = i / HWD, r = i - bb*HWD;
    float l = lam[0];
    float2 c0v = g_c0[i];
    float zr = zk[(bb*2+0)*HWD + r];
    float zi = zk[(bb*2+1)*HWD + r];
    float xr = fmaxf(c0v.x - l*(c0v.x - zr), 0.f);
    float xi = fmaxf(c0v.y - l*(c0v.y - zi), 0.f);
    float2 v = make_float2(xr, xi);
    g_x[i] = v;
    g_y[i] = v;
}

// K1: rows forward FFT of coil*y  -> T1
__global__ void __launch_bounds__(384) k1_rows(const float* __restrict__ csm)
{
    FFT_PREAMBLE
    int blk = blockIdx.x;
    int hq = blk % (HD/4), bc = blk / (HD/4);
    int c = bc % CD, bb = bc / CD;
    int h = hq*4 + g;
    const float*  cre = csm + ((bb*2+0)*CD + c)*HWD + h*WD;
    const float*  cim = csm + ((bb*2+1)*CD + c)*HWD + h*WD;
    const float2* yr  = g_y + (bb*HD + h)*WD;
    #pragma unroll
    for (int j = 0; j < 4; j++) {
        int w = lt + 96*j;
        float2 yv = yr[w];
        float cr = cre[w], ci = cim[w];
        b0[pd(w)] = make_float2(cr*yv.x - ci*yv.y, cr*yv.y + ci*yv.x);
    }
    __syncthreads();
    fft384(b0, b1, stw, lt, 1.0f);
    float2* orow = g_T1 + ((bb*CD + c)*HD + h)*WD;
    #pragma unroll
    for (int j = 0; j < 4; j++) { int w = lt + 96*j; orow[w] = b0[pd(w)]; }
}

// K2: cols forward FFT, mask, cols inverse FFT (in place in T1, /384)
__global__ void __launch_bounds__(384) k2_cols(const int* __restrict__ mask)
{
    FFT_PREAMBLE
    int blk = blockIdx.x;
    int wq = blk % (WD/4), bc = blk / (WD/4);
    int c = bc % CD, bb = bc / CD;
    int w = wq*4 + g;
    float2* base = g_T1 + (bb*CD + c)*HWD;
    #pragma unroll
    for (int j = 0; j < 4; j++) { int h = lt + 96*j; b0[pd(h)] = base[h*WD + w]; }
    __syncthreads();
    fft384(b0, b1, stw, lt, 1.0f);
    const int* mb = mask + bb*HWD;
    #pragma unroll
    for (int j = 0; j < 4; j++) {
        int h = lt + 96*j;
        float mv = (float)mb[h*WD + w];
        float2 v = b0[pd(h)];
        v.x *= mv; v.y *= mv;
        b0[pd(h)] = v;
    }
    __syncthreads();
    fft384(b0, b1, stw, lt, -1.0f);
    const float sc = 1.0f/384.0f;
    #pragma unroll
    for (int j = 0; j < 4; j++) {
        int h = lt + 96*j;
        float2 v = b0[pd(h)];
        base[h*WD + w] = make_float2(v.x*sc, v.y*sc);
    }
}

// K3: rows inverse FFT, * conj(coil), accumulate 4 coils -> S partial (no atomics)
__global__ void __launch_bounds__(384) k3_rows(const float* __restrict__ csm)
{
    FFT_PREAMBLE
    int blk = blockIdx.x;
    int part = blk & 3;
    int rest = blk >> 2;
    int hq = rest % (HD/4), bb = rest / (HD/4);
    int h = hq*4 + g;
    float2 acc[4];
    #pragma unroll
    for (int j = 0; j < 4; j++) acc[j] = make_float2(0.f, 0.f);

    for (int cc = 0; cc < 4; cc++) {
        int c = part*4 + cc;
        const float2* row = g_T1 + ((bb*CD + c)*HD + h)*WD;
        #pragma unroll
        for (int j = 0; j < 4; j++) { int w = lt + 96*j; b0[pd(w)] = row[w]; }
        __syncthreads();
        fft384(b0, b1, stw, lt, -1.0f);
        const float* cre = csm + ((bb*2+0)*CD + c)*HWD + h*WD;
        const float* cim = csm + ((bb*2+1)*CD + c)*HWD + h*WD;
        #pragma unroll
        for (int j = 0; j < 4; j++) {
            int w = lt + 96*j;
            float2 v = b0[pd(w)];
            float cr = cre[w], ci = cim[w];
            // conj(coil)*v
            acc[j].x += cr*v.x + ci*v.y;
            acc[j].y += cr*v.y - ci*v.x;
        }
        __syncthreads();   // protect b0 before next coil's load
    }
    const float sc = 1.0f/384.0f;
    float2* out = g_S + (part*BD + bb)*HWD + h*WD;
    #pragma unroll
    for (int j = 0; j < 4; j++) {
        int w = lt + 96*j;
        out[w] = make_float2(acc[j].x*sc, acc[j].y*sc);
    }
}

// K4: FISTA elementwise update
__global__ void k4_update(const float* __restrict__ zk, const float* __restrict__ lam,
                          float beta)
{
    int i = blockIdx.x*blockDim.x + threadIdx.x;
    if (i >= BD*HWD) return;
    int bb = i / HWD, r = i - bb*HWD;
    const int NP = BD*HWD;
    float Sx = g_S[i].x + g_S[NP+i].x + g_S[2*NP+i].x + g_S[3*NP+i].x;
    float Sy = g_S[i].y + g_S[NP+i].y + g_S[2*NP+i].y + g_S[3*NP+i].y;
    float2 yo = g_y[i], xo = g_x[i], c0v = g_c0[i];
    float l = lam[0];
    float zr = zk[(bb*2+0)*HWD + r];
    float zi = zk[(bb*2+1)*HWD + r];
    // xn = y - (S - c0)
    float xr = yo.x - Sx + c0v.x;
    float xi = yo.y - Sy + c0v.y;
    xr = xr - l*(xr - zr);
    xi = xi - l*(xi - zi);
    xr = fmaxf(xr, 0.f);
    xi = fmaxf(xi, 0.f);
    float yr = xr + beta*(xr - xo.x);
    float yi = xi + beta*(xi - xo.y);
    g_x[i] = make_float2(xr, xi);
    g_y[i] = make_float2(yr, yi);
}

// final output: [B,2,H,W] float
__global__ void k5_out(float* __restrict__ out)
{
    int i = blockIdx.x*blockDim.x + threadIdx.x;
    if (i >= BD*HWD) return;
    int bb = i / HWD, r = i - bb*HWD;
    float2 v = g_x[i];
    out[(bb*2+0)*HWD + r] = v.x;
    out[(bb*2+1)*HWD + r] = v.y;
}

// ---------------- host ----------------
extern "C" void kernel_launch(void* const* d_in, const int* in_sizes, int n_in,
                              void* d_out, int out_size)
{
    const float* zk   = (const float*)d_in[0];   // z_k  [B,2,H,W]
    const float* x0   = (const float*)d_in[1];   // x0   [B,2,H,W]
    const float* csm  = (const float*)d_in[2];   // csm  [B,2,C,H,W]
    const float* lam  = (const float*)d_in[3];   // lam  [1]
    const int*   mask = (const int*)d_in[4];     // mask [B,H,W]
    float* out = (float*)d_out;

    // FISTA t-sequence (host, deterministic)
    float betas[NITER];
    double t = 1.0;
    for (int n = 0; n < NITER; n++) {
        double tn = (1.0 + sqrt(1.0 + 4.0*t*t)) / 2.0;
        betas[n] = (float)((t - 1.0) / tn);
        t = tn;
    }

    const int EW_BLOCKS = (BD*HWD) / 256;       // 2304, exact
    init_tw_kernel<<<1, 384>>>();
    p1_sbar<<<EW_BLOCKS, 256>>>(csm);
    p2_rows<<<BD*(HD/4), 384>>>(x0, mask);
    p3_cols<<<BD*(WD/4), 384>>>();
    k4_first<<<EW_BLOCKS, 256>>>(zk, lam);

    for (int n = 1; n < NITER; n++) {
        k1_rows<<<BD*CD*(HD/4), 384>>>(csm);
        k2_cols<<<BD*CD*(WD/4), 384>>>(mask);
        k3_rows<<<BD*(HD/4)*4, 384>>>(csm);
        k4_update<<<EW_BLOCKS, 256>>>(zk, lam, betas[n]);
    }
    k5_out<<<EW_BLOCKS, 256>>>(out);
}

// round 3
// speedup vs baseline: 1.4112x; 1.4112x over previous
#include <cuda_runtime.h>
#include <math.h>

// Problem dims (hardcoded from reference setup_inputs)
#define BD 4
#define CD 16
#define HD 384
#define WD 384
#define HWD (HD*WD)
#define NITER 20

// ---------------- scratch (device globals; no allocation APIs) ----------------
__device__ float2 g_tw[384];                 // forward twiddles e^{-2pi i t/384}
__device__ float2 g_T1[BD*CD*HWD];           // 75.5 MB k-space scratch
__device__ float2 g_S[4*BD*HWD];             // 4 coil-partials of S(y)
__device__ float2 g_c0[BD*HWD];              // constant adjoint-of-data term
__device__ float2 g_Sbar[BD*HWD];            // sum_c conj(coil)
__device__ float2 g_x[BD*HWD];               // FISTA x state
__device__ float2 g_y[BD*HWD];               // FISTA y state

// ---------------- FFT helpers ----------------
__device__ __forceinline__ int pd(int i) { return i + (i >> 4); }  // bank-conflict pad
#define PBUF 408
// group stride: 2*PBUF (two ping-pong buffers) + 4 skew so stride mod 32 words == 8
// (keeps the coalesced-tile staging stores at <=2-way bank conflicts)
#define GSTRIDE (2*PBUF + 4)
#define NG 4

__device__ __forceinline__ float2 cmulf(float2 a, float2 b) {
    return make_float2(a.x*b.x - a.y*b.y, a.x*b.y + a.y*b.x);
}

// one radix-4 Stockham stage butterfly for thread lt (0..95)
__device__ __forceinline__ void r4(const float2* __restrict__ in, float2* __restrict__ out,
                                   const float2* __restrict__ tw,
                                   int lt, int tbase, int o0, int ostep, float dir)
{
    float2 z0 = in[pd(lt)], z1 = in[pd(lt+96)], z2 = in[pd(lt+192)], z3 = in[pd(lt+288)];
    float ax = z0.x+z2.x, ay = z0.y+z2.y;
    float bx = z0.x-z2.x, by = z0.y-z2.y;
    float cx = z1.x+z3.x, cy = z1.y+z3.y;
    float dx = z1.x-z3.x, dy = z1.y-z3.y;
    float ix =  dir*dy,   iy = -dir*dx;           // (-i*d) fwd, (+i*d) inv
    float2 Z0 = make_float2(ax+cx, ay+cy);
    float2 Z1 = make_float2(bx+ix, by+iy);
    float2 Z2 = make_float2(ax-cx, ay-cy);
    float2 Z3 = make_float2(bx-ix, by-iy);
    out[pd(o0)] = Z0;
    float2 w1 = tw[tbase];    w1.y *= dir;
    float2 w2 = tw[2*tbase];  w2.y *= dir;
    float2 w3 = tw[3*tbase];  w3.y *= dir;
    out[pd(o0 +   ostep)] = cmulf(Z1, w1);
    out[pd(o0 + 2*ostep)] = cmulf(Z2, w2);
    out[pd(o0 + 3*ostep)] = cmulf(Z3, w3);
}

__device__ __forceinline__ void dft3(float2 a, float2 b, float2 c, float S3,
                                     float2& Z0, float2& Z1, float2& Z2)
{
    float tx = b.x+c.x, ty = b.y+c.y;
    float ux = b.x-c.x, uy = b.y-c.y;
    Z0 = make_float2(a.x+tx, a.y+ty);
    float vx = a.x - 0.5f*tx, vy = a.y - 0.5f*ty;
    Z1 = make_float2(vx + S3*uy, vy - S3*ux);
    Z2 = make_float2(vx - S3*uy, vy + S3*ux);
}

// 384-point FFT, Stockham DIF radices [4,4,4,6], 96 threads (lt), in/out in b0.
__device__ __forceinline__ void fft384(float2* b0, float2* b1,
                                       const float2* tw, int lt, float dir)
{
    r4(b0, b1, tw, lt, lt, 4*lt, 1, dir);                      // n=384 s=1
    __syncthreads();
    { int p = lt>>2, q = lt&3;  r4(b1, b0, tw, lt, 4*p,  q+16*p, 4,  dir); }  // n=96 s=4
    __syncthreads();
    { int p = lt>>4, q = lt&15; r4(b0, b1, tw, lt, 16*p, q+64*p, 16, dir); }  // n=24 s=16
    __syncthreads();
    if (lt < 64) {                                             // n=6 radix-6, s=64
        float2 z0 = b1[pd(lt)],     z1 = b1[pd(lt+64)],  z2 = b1[pd(lt+128)];
        float2 z3 = b1[pd(lt+192)], z4 = b1[pd(lt+256)], z5 = b1[pd(lt+320)];
        float S3 = 0.8660254037844386f * dir;
        float2 E0,E1,E2,O0,O1,O2;
        dft3(z0, z2, z4, S3, E0, E1, E2);
        dft3(z1, z3, z5, S3, O0, O1, O2);
        float2 w6a = make_float2( 0.5f, -S3);
        float2 w6b = make_float2(-0.5f, -S3);
        float2 P1 = cmulf(O1, w6a);
        float2 P2 = cmulf(O2, w6b);
        b0[pd(lt)]     = make_float2(E0.x+O0.x, E0.y+O0.y);
        b0[pd(lt+64)]  = make_float2(E1.x+P1.x, E1.y+P1.y);
        b0[pd(lt+128)] = make_float2(E2.x+P2.x, E2.y+P2.y);
        b0[pd(lt+192)] = make_float2(E0.x-O0.x, E0.y-O0.y);
        b0[pd(lt+256)] = make_float2(E1.x-P1.x, E1.y-P1.y);
        b0[pd(lt+320)] = make_float2(E2.x-P2.x, E2.y-P2.y);
    }
    __syncthreads();
}

#define FFT_PREAMBLE                                              \
    __shared__ float2 sb[NG*GSTRIDE];                             \
    __shared__ float2 stw[384];                                   \
    for (int t = threadIdx.x; t < 384; t += 384) stw[t] = g_tw[t];\
    int g  = threadIdx.x / 96;                                    \
    int lt = threadIdx.x % 96;                                    \
    float2* b0 = sb + g*GSTRIDE;                                  \
    float2* b1 = b0 + PBUF;

// ---------------- init ----------------
__global__ void init_tw_kernel()
{
    int t = threadIdx.x;
    if (t < 384) {
        float s, c;
        sincospif(-2.0f * (float)t / 384.0f, &s, &c);
        g_tw[t] = make_float2(c, s);
    }
}

// Sbar = sum_c conj(coil)
__global__ void p1_sbar(const float* __restrict__ csm)
{
    int i = blockIdx.x*blockDim.x + threadIdx.x;
    if (i >= BD*HWD) return;
    int bb = i / HWD, r = i - bb*HWD;
    float sr = 0.f, si = 0.f;
    #pragma unroll
    for (int c = 0; c < CD; c++) {
        sr += csm[((bb*2+0)*CD + c)*HWD + r];
        si -= csm[((bb*2+1)*CD + c)*HWD + r];
    }
    g_Sbar[i] = make_float2(sr, si);
}

// rows inverse FFT of (mask * b)  -> tmp (front of g_T1)
__global__ void __launch_bounds__(384) p2_rows(const float* __restrict__ x0,
                                               const int* __restrict__ mask)
{
    FFT_PREAMBLE
    int blk = blockIdx.x;
    int hq = blk % (HD/4), bb = blk / (HD/4);
    int h = hq*4 + g;
    const float* bre = x0 + (bb*2+0)*HWD + h*WD;
    const float* bim = x0 + (bb*2+1)*HWD + h*WD;
    const int*   mr  = mask + bb*HWD + h*WD;
    #pragma unroll
    for (int j = 0; j < 4; j++) {
        int w = lt + 96*j;
        float mv = (float)mr[w];
        b0[pd(w)] = make_float2(mv*bre[w], mv*bim[w]);
    }
    __syncthreads();
    fft384(b0, b1, stw, lt, -1.0f);
    const float sc = 1.0f/384.0f;
    float2* orow = g_T1 + (bb*HD + h)*WD;
    #pragma unroll
    for (int j = 0; j < 4; j++) {
        int w = lt + 96*j;
        float2 v = b0[pd(w)];
        orow[w] = make_float2(v.x*sc, v.y*sc);
    }
}

// cols inverse FFT of tmp, * Sbar  -> c0  (coalesced column-tile I/O)
__global__ void __launch_bounds__(384) p3_cols()
{
    FFT_PREAMBLE
    int blk = blockIdx.x;
    int wq = blk % (WD/4), bb = blk / (WD/4);
    int w0 = wq*4;
    const float2* base = g_T1 + bb*HWD;
    // coalesced tile load: c fastest -> 32B sectors fully used
    #pragma unroll
    for (int it = 0; it < 4; it++) {
        int idx = threadIdx.x + it*384;
        int c4 = idx & 3, h = idx >> 2;
        sb[c4*GSTRIDE + pd(h)] = base[h*WD + w0 + c4];
    }
    __syncthreads();
    fft384(b0, b1, stw, lt, -1.0f);
    const float sc = 1.0f/384.0f;
    #pragma unroll
    for (int it = 0; it < 4; it++) {
        int idx = threadIdx.x + it*384;
        int c4 = idx & 3, h = idx >> 2;
        float2 v = sb[c4*GSTRIDE + pd(h)];
        v.x *= sc; v.y *= sc;
        float2 sbv = g_Sbar[bb*HWD + h*WD + w0 + c4];
        g_c0[bb*HWD + h*WD + w0 + c4] = cmulf(sbv, v);
    }
}

// iteration 0 (y = 0): x = y = relu((1-lam)*c0 + lam*zc)
__global__ void k4_first(const float* __restrict__ zk, const float* __restrict__ lam)
{
    int i = blockIdx.x*blockDim.x + threadIdx.x;
    if (i >= BD*HWD) return;
    int bb = i / HWD, r = i - bb*HWD;
    float l = lam[0];
    float2 c0v = g_c0[i];
    float zr = zk[(bb*2+0)*HWD + r];
    float zi = zk[(bb*2+1)*HWD + r];
    float xr = fmaxf(c0v.x - l*(c0v.x - zr), 0.f);
    float xi = fmaxf(c0v.y - l*(c0v.y - zi), 0.f);
    float2 v = make_float2(xr, xi);
    g_x[i] = v;
    g_y[i] = v;
}

// K1: rows forward FFT of coil*y  -> T1
__global__ void __launch_bounds__(384) k1_rows(const float* __restrict__ csm)
{
    FFT_PREAMBLE
    int blk = blockIdx.x;
    int hq = blk % (HD/4), bc = blk / (HD/4);
    int c = bc % CD, bb = bc / CD;
    int h = hq*4 + g;
    const float*  cre = csm + ((bb*2+0)*CD + c)*HWD + h*WD;
    const float*  cim = csm + ((bb*2+1)*CD + c)*HWD + h*WD;
    const float2* yr  = g_y + (bb*HD + h)*WD;
    #pragma unroll
    for (int j = 0; j < 4; j++) {
        int w = lt + 96*j;
        float2 yv = yr[w];
        float cr = cre[w], ci = cim[w];
        b0[pd(w)] = make_float2(cr*yv.x - ci*yv.y, cr*yv.y + ci*yv.x);
    }
    __syncthreads();
    fft384(b0, b1, stw, lt, 1.0f);
    float2* orow = g_T1 + ((bb*CD + c)*HD + h)*WD;
    #pragma unroll
    for (int j = 0; j < 4; j++) { int w = lt + 96*j; orow[w] = b0[pd(w)]; }
}

// K2: cols forward FFT, mask, cols inverse FFT (in place in T1, /384)
// All global I/O uses the coalesced column-tile mapping.
__global__ void __launch_bounds__(384) k2_cols(const int* __restrict__ mask)
{
    FFT_PREAMBLE
    int blk = blockIdx.x;
    int wq = blk % (WD/4), bc = blk / (WD/4);
    int c = bc % CD, bb = bc / CD;
    int w0 = wq*4;
    float2* base = g_T1 + (bb*CD + c)*HWD;
    #pragma unroll
    for (int it = 0; it < 4; it++) {
        int idx = threadIdx.x + it*384;
        int c4 = idx & 3, h = idx >> 2;
        sb[c4*GSTRIDE + pd(h)] = base[h*WD + w0 + c4];
    }
    __syncthreads();
    fft384(b0, b1, stw, lt, 1.0f);
    const int* mb = mask + bb*HWD;
    #pragma unroll
    for (int it = 0; it < 4; it++) {
        int idx = threadIdx.x + it*384;
        int c4 = idx & 3, h = idx >> 2;
        float mv = (float)mb[h*WD + w0 + c4];
        float2 v = sb[c4*GSTRIDE + pd(h)];
        v.x *= mv; v.y *= mv;
        sb[c4*GSTRIDE + pd(h)] = v;
    }
    __syncthreads();
    fft384(b0, b1, stw, lt, -1.0f);
    const float sc = 1.0f/384.0f;
    #pragma unroll
    for (int it = 0; it < 4; it++) {
        int idx = threadIdx.x + it*384;
        int c4 = idx & 3, h = idx >> 2;
        float2 v = sb[c4*GSTRIDE + pd(h)];
        base[h*WD + w0 + c4] = make_float2(v.x*sc, v.y*sc);
    }
}

// K3: rows inverse FFT, * conj(coil), accumulate 4 coils -> S partial (no atomics)
__global__ void __launch_bounds__(384) k3_rows(const float* __restrict__ csm)
{
    FFT_PREAMBLE
    int blk = blockIdx.x;
    int part = blk & 3;
    int rest = blk >> 2;
    int hq = rest % (HD/4), bb = rest / (HD/4);
    int h = hq*4 + g;
    float2 acc[4];
    #pragma unroll
    for (int j = 0; j < 4; j++) acc[j] = make_float2(0.f, 0.f);

    for (int cc = 0; cc < 4; cc++) {
        int c = part*4 + cc;
        const float2* row = g_T1 + ((bb*CD + c)*HD + h)*WD;
        #pragma unroll
        for (int j = 0; j < 4; j++) { int w = lt + 96*j; b0[pd(w)] = row[w]; }
        __syncthreads();
        fft384(b0, b1, stw, lt, -1.0f);
        const float* cre = csm + ((bb*2+0)*CD + c)*HWD + h*WD;
        const float* cim = csm + ((bb*2+1)*CD + c)*HWD + h*WD;
        #pragma unroll
        for (int j = 0; j < 4; j++) {
            int w = lt + 96*j;
            float2 v = b0[pd(w)];
            float cr = cre[w], ci = cim[w];
            acc[j].x += cr*v.x + ci*v.y;
            acc[j].y += cr*v.y - ci*v.x;
        }
        __syncthreads();   // protect b0 before next coil's load
    }
    const float sc = 1.0f/384.0f;
    float2* out = g_S + (part*BD + bb)*HWD + h*WD;
    #pragma unroll
    for (int j = 0; j < 4; j++) {
        int w = lt + 96*j;
        out[w] = make_float2(acc[j].x*sc, acc[j].y*sc);
    }
}

// K4: FISTA elementwise update
__global__ void k4_update(const float* __restrict__ zk, const float* __restrict__ lam,
                          float beta)
{
    int i = blockIdx.x*blockDim.x + threadIdx.x;
    if (i >= BD*HWD) return;
    int bb = i / HWD, r = i - bb*HWD;
    const int NP = BD*HWD;
    float Sx = g_S[i].x + g_S[NP+i].x + g_S[2*NP+i].x + g_S[3*NP+i].x;
    float Sy = g_S[i].y + g_S[NP+i].y + g_S[2*NP+i].y + g_S[3*NP+i].y;
    float2 yo = g_y[i], xo = g_x[i], c0v = g_c0[i];
    float l = lam[0];
    float zr = zk[(bb*2+0)*HWD + r];
    float zi = zk[(bb*2+1)*HWD + r];
    float xr = yo.x - Sx + c0v.x;
    float xi = yo.y - Sy + c0v.y;
    xr = xr - l*(xr - zr);
    xi = xi - l*(xi - zi);
    xr = fmaxf(xr, 0.f);
    xi = fmaxf(xi, 0.f);
    float yr = xr + beta*(xr - xo.x);
    float yi = xi + beta*(xi - xo.y);
    g_x[i] = make_float2(xr, xi);
    g_y[i] = make_float2(yr, yi);
}

// final output: [B,2,H,W] float
__global__ void k5_out(float* __restrict__ out)
{
    int i = blockIdx.x*blockDim.x + threadIdx.x;
    if (i >= BD*HWD) return;
    int bb = i / HWD, r = i - bb*HWD;
    float2 v = g_x[i];
    out[(bb*2+0)*HWD + r] = v.x;
    out[(bb*2+1)*HWD + r] = v.y;
}

// ---------------- host ----------------
extern "C" void kernel_launch(void* const* d_in, const int* in_sizes, int n_in,
                              void* d_out, int out_size)
{
    const float* zk   = (const float*)d_in[0];   // z_k  [B,2,H,W]
    const float* x0   = (const float*)d_in[1];   // x0   [B,2,H,W]
    const float* csm  = (const float*)d_in[2];   // csm  [B,2,C,H,W]
    const float* lam  = (const float*)d_in[3];   // lam  [1]
    const int*   mask = (const int*)d_in[4];     // mask [B,H,W]
    float* out = (float*)d_out;

    // FISTA t-sequence (host, deterministic)
    float betas[NITER];
    double t = 1.0;
    for (int n = 0; n < NITER; n++) {
        double tn = (1.0 + sqrt(1.0 + 4.0*t*t)) / 2.0;
        betas[n] = (float)((t - 1.0) / tn);
        t = tn;
    }

    const int EW_BLOCKS = (BD*HWD) / 256;       // 2304, exact
    init_tw_kernel<<<1, 384>>>();
    p1_sbar<<<EW_BLOCKS, 256>>>(csm);
    p2_rows<<<BD*(HD/4), 384>>>(x0, mask);
    p3_cols<<<BD*(WD/4), 384>>>();
    k4_first<<<EW_BLOCKS, 256>>>(zk, lam);

    for (int n = 1; n < NITER; n++) {
        k1_rows<<<BD*CD*(HD/4), 384>>>(csm);
        k2_cols<<<BD*CD*(WD/4), 384>>>(mask);
        k3_rows<<<BD*(HD/4)*4, 384>>>(csm);
        k4_update<<<EW_BLOCKS, 256>>>(zk, lam, betas[n]);
    }
    k5_out<<<EW_BLOCKS, 256>>>(out);
}

// round 4
// speedup vs baseline: 1.7835x; 1.2638x over previous
#include <cuda_runtime.h>
#include <math.h>

// Problem dims (hardcoded from reference setup_inputs)
#define BD 4
#define CD 16
#define HD 384
#define WD 384
#define HWD (HD*WD)
#define NITER 20

#define C30 0.86602540378443865f

// ---------------- scratch (device globals; no allocation APIs) ----------------
__device__ float2 g_tw[384];                 // W384^t = exp(-2pi i t/384)
__device__ float2 g_T1[BD*CD*HWD];           // k-space scratch (w-index permuted)
__device__ float2 g_S[4*BD*HWD];             // 4 coil-partials of S(y)
__device__ float2 g_c0[BD*HWD];              // constant adjoint-of-data term
__device__ float2 g_Sbar[BD*HWD];            // sum_c conj(coil)
__device__ float2 g_x[BD*HWD];               // FISTA x state
__device__ float2 g_y[BD*HWD];               // FISTA y state
__device__ float  g_PM[BD*HWD];              // permuted mask * (1/384)

// ---------------- complex helpers ----------------
__device__ __forceinline__ float2 cmulf(float2 a, float2 b) {
    return make_float2(a.x*b.x - a.y*b.y, a.x*b.y + a.y*b.x);
}
__device__ __forceinline__ float2 cmul_cs(float2 z, float cr, float ci) {
    return make_float2(z.x*cr - z.y*ci, z.x*ci + z.y*cr);
}
__device__ __forceinline__ int br5(int x) { return (int)(__brev((unsigned)x) >> 27); }
// storage index s (0..383) -> true frequency index
__device__ __forceinline__ int permi(int s) { return (s >> 5) + 12*br5(s & 31); }

__device__ __forceinline__ float2 shfl_xor_c(float2 v, int m) {
    float2 r;
    r.x = __shfl_xor_sync(0xffffffffu, v.x, m);
    r.y = __shfl_xor_sync(0xffffffffu, v.y, m);
    return r;
}

// ---------------- per-lane 12-point DFT (in place) ----------------
// v'[j] = sum_k v[k] * W12^{d*j*k}
__device__ __forceinline__ void dft12(float2* v, float d)
{
    float2 t0[4], t1[4], t2[4];
#pragma unroll
    for (int b = 0; b < 3; b++) {
        float2 A0 = v[b], A1 = v[b+3], A2 = v[b+6], A3 = v[b+9];
        float2 s02 = make_float2(A0.x+A2.x, A0.y+A2.y);
        float2 d02 = make_float2(A0.x-A2.x, A0.y-A2.y);
        float2 s13 = make_float2(A1.x+A3.x, A1.y+A3.y);
        float2 d13 = make_float2(A1.x-A3.x, A1.y-A3.y);
        float2 rot = make_float2(d*d13.y, -d*d13.x);
        float2* t = (b == 0) ? t0 : (b == 1) ? t1 : t2;
        t[0] = make_float2(s02.x+s13.x, s02.y+s13.y);
        t[2] = make_float2(s02.x-s13.x, s02.y-s13.y);
        t[1] = make_float2(d02.x+rot.x, d02.y+rot.y);
        t[3] = make_float2(d02.x-rot.x, d02.y-rot.y);
    }
    const float CR[12] = {1.f,  C30,  .5f, 0.f, -.5f, -C30, -1.f, -C30, -.5f,  0.f,  .5f,  C30};
    const float SI[12] = {0.f,  .5f,  C30, 1.f,  C30,  .5f,  0.f, -.5f, -C30, -1.f, -C30, -.5f};
#pragma unroll
    for (int j = 0; j < 12; j++) {
        int m2 = (2*j) % 12;
        float2 a = (j&3)==0 ? t0[0] : (j&3)==1 ? t0[1] : (j&3)==2 ? t0[2] : t0[3];
        float2 b = (j&3)==0 ? t1[0] : (j&3)==1 ? t1[1] : (j&3)==2 ? t1[2] : t1[3];
        float2 c = (j&3)==0 ? t2[0] : (j&3)==1 ? t2[1] : (j&3)==2 ? t2[2] : t2[3];
        b = cmul_cs(b, CR[j],  -d*SI[j]);
        c = cmul_cs(c, CR[m2], -d*SI[m2]);
        v[j] = make_float2(a.x+b.x+c.x, a.y+b.y+c.y);
    }
}

// ---------------- four-step twiddle: v[j] *= W384^{d*l*j} ----------------
__device__ __forceinline__ void twiddle384(float2* v, int l, float d, const float2* stw)
{
    float2 w1 = stw[l];     w1.y *= d;
    float2 w2 = stw[2*l];   w2.y *= d;
    float2 w3 = stw[3*l];   w3.y *= d;
    float2 w4  = cmulf(w2, w2);
    float2 w5  = cmulf(w2, w3);
    float2 w6  = cmulf(w3, w3);
    float2 w7  = cmulf(w3, w4);
    float2 w8  = cmulf(w4, w4);
    float2 w9  = cmulf(w4, w5);
    float2 w10 = cmulf(w5, w5);
    float2 w11 = cmulf(w5, w6);
    v[1]  = cmulf(v[1],  w1);
    v[2]  = cmulf(v[2],  w2);
    v[3]  = cmulf(v[3],  w3);
    v[4]  = cmulf(v[4],  w4);
    v[5]  = cmulf(v[5],  w5);
    v[6]  = cmulf(v[6],  w6);
    v[7]  = cmulf(v[7],  w7);
    v[8]  = cmulf(v[8],  w8);
    v[9]  = cmulf(v[9],  w9);
    v[10] = cmulf(v[10], w10);
    v[11] = cmulf(v[11], w11);
}

// ---------------- cross-lane 32-pt FFT, radix-2 DIF (natural in -> bitrev out) ----
__device__ __forceinline__ void dif_stages(float2* v, int l, float d, const float2* stw)
{
#pragma unroll
    for (int st = 0; st < 5; st++) {
        const int H = 16 >> st;
        bool up = (l & H) != 0;
        float sgn = up ? -1.f : 1.f;
        float2 w = make_float2(1.f, 0.f);
        if (H > 1) { w = stw[(192/H) * (l & (H-1))]; w.y *= d; }
#pragma unroll
        for (int j = 0; j < 12; j++) {
            float2 p = shfl_xor_c(v[j], H);
            float2 t = make_float2(p.x + sgn*v[j].x, p.y + sgn*v[j].y);
            if (H > 1) v[j] = up ? cmulf(t, w) : t;
            else       v[j] = t;
        }
    }
}

// ---------------- cross-lane 32-pt FFT, radix-2 DIT (bitrev in -> natural out) ----
__device__ __forceinline__ void dit_stages(float2* v, int l, float d, const float2* stw)
{
#pragma unroll
    for (int st = 0; st < 5; st++) {
        const int H = 1 << st;
        bool up = (l & H) != 0;
        float2 w = make_float2(1.f, 0.f);
        if (H > 1) { w = stw[(192/H) * (l & (H-1))]; w.y *= d; }
#pragma unroll
        for (int j = 0; j < 12; j++) {
            float2 p = shfl_xor_c(v[j], H);
            float2 src = up ? v[j] : p;
            float2 t = (H > 1) ? cmulf(w, src) : src;
            v[j] = up ? make_float2(p.x - t.x, p.y - t.y)
                      : make_float2(v[j].x + t.x, v[j].y + t.y);
        }
    }
}

// full 384-pt, natural input (reg k = x[l+32k]) -> permuted output
// (reg j at lane l = X[j + 12*br5(l)]); dir=+1 fwd, -1 inverse (unnormalized)
__device__ __forceinline__ void fft_dif(float2* v, int l, float d, const float2* stw)
{
    dft12(v, d);
    twiddle384(v, l, d, stw);
    dif_stages(v, l, d, stw);
}
// full 384-pt, permuted input (reg j at lane l = Y[j + 12*br5(l)]) -> natural output
__device__ __forceinline__ void fft_dit(float2* v, int l, float d, const float2* stw)
{
    dit_stages(v, l, d, stw);
    twiddle384(v, l, d, stw);
    dft12(v, d);
}

#define LOAD_STW                                                    \
    __shared__ float2 stw[384];                                     \
    for (int t_ = threadIdx.x; t_ < 384; t_ += blockDim.x) stw[t_] = g_tw[t_];

// ---------------- init ----------------
__global__ void init_tw_kernel()
{
    int t = threadIdx.x;
    if (t < 384) {
        float s, c;
        sincospif(-2.0f * (float)t / 384.0f, &s, &c);
        g_tw[t] = make_float2(c, s);
    }
}

// Sbar = sum_c conj(coil)
__global__ void p1_sbar(const float* __restrict__ csm)
{
    int i = blockIdx.x*blockDim.x + threadIdx.x;
    if (i >= BD*HWD) return;
    int bb = i / HWD, r = i - bb*HWD;
    float sr = 0.f, si = 0.f;
#pragma unroll
    for (int c = 0; c < CD; c++) {
        sr += csm[((bb*2+0)*CD + c)*HWD + r];
        si -= csm[((bb*2+1)*CD + c)*HWD + r];
    }
    g_Sbar[i] = make_float2(sr, si);
}

// permuted mask (both axes) premultiplied by 1/384
__global__ void pmask_kernel(const int* __restrict__ mask)
{
    int i = blockIdx.x*blockDim.x + threadIdx.x;
    if (i >= BD*HWD) return;
    int bb = i / HWD, r = i - bb*HWD;
    int sh = r / WD, sw = r - sh*WD;
    g_PM[i] = (float)mask[bb*HWD + permi(sh)*WD + permi(sw)] * (1.0f/384.0f);
}

// prologue: rows inverse FFT of (mask*b)/384 -> T1 (permuted w storage)
__global__ void __launch_bounds__(256) p2_rows(const float* __restrict__ x0,
                                               const int* __restrict__ mask)
{
    LOAD_STW
    __syncthreads();
    int wid = threadIdx.x >> 5, l = threadIdx.x & 31;
    int task = blockIdx.x*8 + wid;                 // (bb,h)
    int h = task % HD, bb = task / HD;
    const float* bre = x0 + (bb*2+0)*HWD + h*WD;
    const float* bim = x0 + (bb*2+1)*HWD + h*WD;
    const int*   mr  = mask + bb*HWD + h*WD;
    float2 v[12];
#pragma unroll
    for (int k = 0; k < 12; k++) {
        int w = l + 32*k;
        float mv = (float)mr[w] * (1.0f/384.0f);
        v[k] = make_float2(mv*bre[w], mv*bim[w]);
    }
    fft_dif(v, l, -1.f, stw);
    float2* orow = g_T1 + (bb*HD + h)*WD;
#pragma unroll
    for (int j = 0; j < 12; j++) orow[j*32 + l] = v[j];
}

#define KST 388  // float2 stride per column in staging tile

// prologue: cols inverse FFT, * Sbar/384 -> c0 (natural layout, scatter-store)
__global__ void __launch_bounds__(256) p3_cols()
{
    LOAD_STW
    __shared__ float2 tile[8*KST];
    int wid = threadIdx.x >> 5, l = threadIdx.x & 31;
    int wq = blockIdx.x % (WD/8), bb = blockIdx.x / (WD/8);
    int sw0 = wq*8;
    const float2* base = g_T1 + bb*HWD;
#pragma unroll
    for (int i = 0; i < 12; i++) {
        int idx = threadIdx.x + i*256;
        int cc = idx & 7, hh = idx >> 3;
        tile[cc*KST + hh] = base[hh*WD + sw0 + cc];
    }
    __syncthreads();
    float2 v[12];
#pragma unroll
    for (int k = 0; k < 12; k++) v[k] = tile[wid*KST + l + 32*k];
    __syncthreads();
    fft_dif(v, l, -1.f, stw);
    // un-permute into natural h positions
#pragma unroll
    for (int j = 0; j < 12; j++) tile[wid*KST + (j + 12*br5(l))] = v[j];
    __syncthreads();
#pragma unroll
    for (int i = 0; i < 12; i++) {
        int idx = threadIdx.x + i*256;
        int cc = idx & 7, hh = idx >> 3;
        int wt = permi(sw0 + cc);
        float2 val = tile[cc*KST + hh];
        val.x *= (1.0f/384.0f); val.y *= (1.0f/384.0f);
        float2 sbv = g_Sbar[bb*HWD + hh*WD + wt];
        g_c0[bb*HWD + hh*WD + wt] = cmulf(sbv, val);
    }
}

// iteration 0 (y = 0): x = y = relu((1-lam)*c0 + lam*zc)
__global__ void k4_first(const float* __restrict__ zk, const float* __restrict__ lam)
{
    int i = blockIdx.x*blockDim.x + threadIdx.x;
    if (i >= BD*HWD) return;
    int bb = i / HWD, r = i - bb*HWD;
    float ll = lam[0];
    float2 c0v = g_c0[i];
    float zr = zk[(bb*2+0)*HWD + r];
    float zi = zk[(bb*2+1)*HWD + r];
    float xr = fmaxf(c0v.x - ll*(c0v.x - zr), 0.f);
    float xi = fmaxf(c0v.y - ll*(c0v.y - zi), 0.f);
    float2 v = make_float2(xr, xi);
    g_x[i] = v;
    g_y[i] = v;
}

// K1: rows forward FFT of coil*y -> T1 (permuted w storage). No smem data path.
__global__ void __launch_bounds__(256) k1_rows(const float* __restrict__ csm)
{
    LOAD_STW
    __syncthreads();
    int wid = threadIdx.x >> 5, l = threadIdx.x & 31;
    int task = blockIdx.x*8 + wid;                 // (bb,c,h)
    int h = task % HD;
    int bc = task / HD;
    int c = bc % CD, bb = bc / CD;
    const float*  cre = csm + ((bb*2+0)*CD + c)*HWD + h*WD;
    const float*  cim = csm + ((bb*2+1)*CD + c)*HWD + h*WD;
    const float2* yr  = g_y + (bb*HD + h)*WD;
    float2 v[12];
#pragma unroll
    for (int k = 0; k < 12; k++) {
        int w = l + 32*k;
        float2 yv = yr[w];
        float a = cre[w], b = cim[w];
        v[k] = make_float2(a*yv.x - b*yv.y, a*yv.y + b*yv.x);
    }
    fft_dif(v, l, 1.f, stw);
    float2* orow = g_T1 + ((bb*CD + c)*HD + h)*WD;
#pragma unroll
    for (int j = 0; j < 12; j++) orow[j*32 + l] = v[j];
}

// K2: cols fwd FFT, permuted-mask multiply (with 1/384), cols inverse FFT, in place.
__global__ void __launch_bounds__(256) k2_cols()
{
    LOAD_STW
    __shared__ float2 tile[8*KST];
    int wid = threadIdx.x >> 5, l = threadIdx.x & 31;
    int wq = blockIdx.x % (WD/8);
    int bc = blockIdx.x / (WD/8);
    int c = bc % CD, bb = bc / CD;
    int sw0 = wq*8;
    float2* base = g_T1 + (bb*CD + c)*HWD;
#pragma unroll
    for (int i = 0; i < 12; i++) {
        int idx = threadIdx.x + i*256;
        int cc = idx & 7, hh = idx >> 3;
        tile[cc*KST + hh] = base[hh*WD + sw0 + cc];
    }
    __syncthreads();
    float2 v[12];
#pragma unroll
    for (int k = 0; k < 12; k++) v[k] = tile[wid*KST + l + 32*k];
    __syncthreads();
    // issue PM loads (to regs) so they overlap the forward FFT
    float pmr[12];
    const float* PM = g_PM + bb*HWD;
#pragma unroll
    for (int i = 0; i < 12; i++) {
        int idx = threadIdx.x + i*256;
        int cc = idx & 7, sh = idx >> 3;
        pmr[i] = PM[sh*WD + sw0 + cc];
    }
    fft_dif(v, l, 1.f, stw);
    // stage PM into smem (reuse tile region as float, stride 392)
    float* tf = (float*)tile;
#pragma unroll
    for (int i = 0; i < 12; i++) {
        int idx = threadIdx.x + i*256;
        int cc = idx & 7, sh = idx >> 3;
        tf[cc*392 + sh] = pmr[i];
    }
    __syncthreads();
#pragma unroll
    for (int j = 0; j < 12; j++) {
        float m = tf[wid*392 + j*32 + l];
        v[j].x *= m; v[j].y *= m;
    }
    __syncthreads();          // all PM reads done before tile reuse
    fft_dit(v, l, -1.f, stw);
#pragma unroll
    for (int k = 0; k < 12; k++) tile[wid*KST + l + 32*k] = v[k];
    __syncthreads();
#pragma unroll
    for (int i = 0; i < 12; i++) {
        int idx = threadIdx.x + i*256;
        int cc = idx & 7, hh = idx >> 3;
        base[hh*WD + sw0 + cc] = tile[cc*KST + hh];
    }
}

// K3: rows inverse FFT (consumes permuted storage directly), * conj(coil)/384,
// accumulate 4 coils -> S partial. No smem data path.
__global__ void __launch_bounds__(256) k3_rows(const float* __restrict__ csm)
{
    LOAD_STW
    __syncthreads();
    int wid = threadIdx.x >> 5, l = threadIdx.x & 31;
    int task = blockIdx.x*8 + wid;                 // (part,bb,h)
    int h = task % HD;
    int rest = task / HD;                          // 0..15
    int bb = rest & 3, part = rest >> 2;
    float2 acc[12];
#pragma unroll
    for (int k = 0; k < 12; k++) acc[k] = make_float2(0.f, 0.f);

    for (int cc = 0; cc < 4; cc++) {
        int c = part*4 + cc;
        const float2* row = g_T1 + ((bb*CD + c)*HD + h)*WD;
        float2 v[12];
#pragma unroll
        for (int j = 0; j < 12; j++) v[j] = row[j*32 + l];
        fft_dit(v, l, -1.f, stw);
        const float* cre = csm + ((bb*2+0)*CD + c)*HWD + h*WD;
        const float* cim = csm + ((bb*2+1)*CD + c)*HWD + h*WD;
#pragma unroll
        for (int k = 0; k < 12; k++) {
            int w = l + 32*k;
            float a = cre[w], b = cim[w];
            acc[k].x += a*v[k].x + b*v[k].y;       // conj(coil)*v
            acc[k].y += a*v[k].y - b*v[k].x;
        }
    }
    const float sc = 1.0f/384.0f;
    float2* out = g_S + (part*BD + bb)*HWD + h*WD;
#pragma unroll
    for (int k = 0; k < 12; k++) {
        int w = l + 32*k;
        out[w] = make_float2(acc[k].x*sc, acc[k].y*sc);
    }
}

// K4: FISTA elementwise update
__global__ void k4_update(const float* __restrict__ zk, const float* __restrict__ lam,
                          float beta)
{
    int i = blockIdx.x*blockDim.x + threadIdx.x;
    if (i >= BD*HWD) return;
    int bb = i / HWD, r = i - bb*HWD;
    const int NP = BD*HWD;
    float Sx = g_S[i].x + g_S[NP+i].x + g_S[2*NP+i].x + g_S[3*NP+i].x;
    float Sy = g_S[i].y + g_S[NP+i].y + g_S[2*NP+i].y + g_S[3*NP+i].y;
    float2 yo = g_y[i], xo = g_x[i], c0v = g_c0[i];
    float ll = lam[0];
    float zr = zk[(bb*2+0)*HWD + r];
    float zi = zk[(bb*2+1)*HWD + r];
    float xr = yo.x - Sx + c0v.x;
    float xi = yo.y - Sy + c0v.y;
    xr = xr - ll*(xr - zr);
    xi = xi - ll*(xi - zi);
    xr = fmaxf(xr, 0.f);
    xi = fmaxf(xi, 0.f);
    float yr = xr + beta*(xr - xo.x);
    float yi = xi + beta*(xi - xo.y);
    g_x[i] = make_float2(xr, xi);
    g_y[i] = make_float2(yr, yi);
}

// final output: [B,2,H,W] float
__global__ void k5_out(float* __restrict__ out)
{
    int i = blockIdx.x*blockDim.x + threadIdx.x;
    if (i >= BD*HWD) return;
    int bb = i / HWD, r = i - bb*HWD;
    float2 v = g_x[i];
    out[(bb*2+0)*HWD + r] = v.x;
    out[(bb*2+1)*HWD + r] = v.y;
}

// ---------------- host ----------------
extern "C" void kernel_launch(void* const* d_in, const int* in_sizes, int n_in,
                              void* d_out, int out_size)
{
    const float* zk   = (const float*)d_in[0];   // z_k  [B,2,H,W]
    const float* x0   = (const float*)d_in[1];   // x0   [B,2,H,W]
    const float* csm  = (const float*)d_in[2];   // csm  [B,2,C,H,W]
    const float* lam  = (const float*)d_in[3];   // lam  [1]
    const int*   mask = (const int*)d_in[4];     // mask [B,H,W]
    float* out = (float*)d_out;

    // FISTA t-sequence (host, deterministic)
    float betas[NITER];
    double t = 1.0;
    for (int n = 0; n < NITER; n++) {
        double tn = (1.0 + sqrt(1.0 + 4.0*t*t)) / 2.0;
        betas[n] = (float)((t - 1.0) / tn);
        t = tn;
    }

    const int EW_BLOCKS = (BD*HWD) / 256;        // 2304, exact
    init_tw_kernel<<<1, 384>>>();
    p1_sbar<<<EW_BLOCKS, 256>>>(csm);
    pmask_kernel<<<EW_BLOCKS, 256>>>(mask);
    p2_rows<<<BD*HD/8, 256>>>(x0, mask);         // 192
    p3_cols<<<BD*(WD/8), 256>>>();               // 192
    k4_first<<<EW_BLOCKS, 256>>>(zk, lam);

    for (int n = 1; n < NITER; n++) {
        k1_rows<<<BD*CD*HD/8, 256>>>(csm);       // 3072
        k2_cols<<<BD*CD*(WD/8), 256>>>();        // 3072
        k3_rows<<<4*BD*HD/8, 256>>>(csm);        // 768
        k4_update<<<EW_BLOCKS, 256>>>(zk, lam, betas[n]);
    }
    k5_out<<<EW_BLOCKS, 256>>>(out);
}